// round 6
// baseline (speedup 1.0000x reference)
#include <cuda_runtime.h>
#include <cuda_bf16.h>

#define N_NODES 50000
#define E_EDGES 1600000
#define E_TOT   (E_EDGES + N_NODES)
#define C       128
#define SCAN_NB ((N_NODES + 1023) / 1024)   // 49 scan blocks

// ---------------- scratch (device globals) ---------------------------------
__device__ float g_h[N_NODES * C];       // 25.6 MB  h = x @ W
__device__ float g_as[N_NODES];          // alpha_src per node
__device__ float g_ad[N_NODES];          // alpha_dst per node
__device__ int   g_cnt[N_NODES];         // degree histogram
__device__ int   g_rowstart[N_NODES + 1];
__device__ int   g_cursor[N_NODES];
__device__ int   g_csr_src[E_TOT];       // 6.6 MB: src node per CSR slot
__device__ int   g_blocksum[64];
__device__ int   g_blockoff[64];

// ---------------- zero histogram -------------------------------------------
__global__ void k_zero() {
    int i = blockIdx.x * blockDim.x + threadIdx.x;
    if (i < N_NODES) g_cnt[i] = 0;
}

// ---------------- fused GEMM + attention dots ------------------------------
__global__ __launch_bounds__(256) void k_gemm(
    const float* __restrict__ x, const float* __restrict__ W,
    const float* __restrict__ a_src, const float* __restrict__ a_dst)
{
    __shared__ float Ws[64][128];   // 32 KB
    __shared__ float xs[64][64];    // 16 KB

    const int tid  = threadIdx.x;
    const int lane = tid & 31;
    const int warp = tid >> 5;
    const int rowBase = blockIdx.x * 64;

    float acc[8][4];
#pragma unroll
    for (int r = 0; r < 8; r++)
#pragma unroll
        for (int c = 0; c < 4; c++) acc[r][c] = 0.f;

    for (int kc = 0; kc < 2; kc++) {
        const float4* Wg  = (const float4*)(W + kc * 64 * C);
        float4*       Wsv = (float4*)&Ws[0][0];
#pragma unroll
        for (int i = 0; i < 8; i++) Wsv[tid + 256 * i] = Wg[tid + 256 * i];
#pragma unroll
        for (int i = 0; i < 4; i++) {
            int idx = tid + 256 * i;
            int r   = idx >> 4;
            int f   = idx & 15;
            int grow = rowBase + r;
            float4 v = make_float4(0.f, 0.f, 0.f, 0.f);
            if (grow < N_NODES)
                v = *(const float4*)(x + (size_t)grow * C + kc * 64 + f * 4);
            ((float4*)&xs[r][0])[f] = v;
        }
        __syncthreads();
#pragma unroll
        for (int kk = 0; kk < 64; kk++) {
            float4 wv = *(const float4*)&Ws[kk][lane * 4];
#pragma unroll
            for (int r = 0; r < 8; r++) {
                float xv = xs[warp * 8 + r][kk];
                acc[r][0] = fmaf(xv, wv.x, acc[r][0]);
                acc[r][1] = fmaf(xv, wv.y, acc[r][1]);
                acc[r][2] = fmaf(xv, wv.z, acc[r][2]);
                acc[r][3] = fmaf(xv, wv.w, acc[r][3]);
            }
        }
        __syncthreads();
    }

    const float4 av = *(const float4*)(a_src + lane * 4);
    const float4 bv = *(const float4*)(a_dst + lane * 4);
#pragma unroll
    for (int r = 0; r < 8; r++) {
        int grow = rowBase + warp * 8 + r;
        float s = acc[r][0]*av.x + acc[r][1]*av.y + acc[r][2]*av.z + acc[r][3]*av.w;
        float d = acc[r][0]*bv.x + acc[r][1]*bv.y + acc[r][2]*bv.z + acc[r][3]*bv.w;
#pragma unroll
        for (int off = 16; off; off >>= 1) {
            s += __shfl_xor_sync(0xffffffffu, s, off);
            d += __shfl_xor_sync(0xffffffffu, d, off);
        }
        if (grow < N_NODES) {
            *(float4*)(g_h + (size_t)grow * C + lane * 4) =
                make_float4(acc[r][0], acc[r][1], acc[r][2], acc[r][3]);
            if (lane == 0) { g_as[grow] = s; g_ad[grow] = d; }
        }
    }
}

// ---------------- CSR build: histogram -------------------------------------
__global__ void k_count(const int* __restrict__ ei) {
    int i = blockIdx.x * blockDim.x + threadIdx.x;
    int stride = gridDim.x * blockDim.x;
    for (int e = i; e < E_TOT; e += stride) {
        int d = (e < E_EDGES) ? __ldg(ei + E_EDGES + e) : (e - E_EDGES);
        atomicAdd(&g_cnt[d], 1);
    }
}

// ---------------- scan phase 1: per-block exclusive scan -------------------
// 49 blocks x 1024 threads; each block scans 1024 counters, writes the
// block-local exclusive prefix into g_rowstart and the block total.
__global__ __launch_bounds__(1024) void k_scan1() {
    __shared__ int warp_sums[32];
    const int tid = threadIdx.x, lane = tid & 31, wid = tid >> 5;
    const int i = blockIdx.x * 1024 + tid;
    int v = (i < N_NODES) ? g_cnt[i] : 0;

    int x = v;
#pragma unroll
    for (int off = 1; off < 32; off <<= 1) {
        int y = __shfl_up_sync(0xffffffffu, x, off);
        if (lane >= off) x += y;
    }
    if (lane == 31) warp_sums[wid] = x;
    __syncthreads();
    if (wid == 0) {
        int w = warp_sums[lane];
        int xw = w;
#pragma unroll
        for (int off = 1; off < 32; off <<= 1) {
            int y = __shfl_up_sync(0xffffffffu, xw, off);
            if (lane >= off) xw += y;
        }
        warp_sums[lane] = xw - w;     // exclusive warp offsets
        if (lane == 31) g_blocksum[blockIdx.x] = xw;   // block total
    }
    __syncthreads();
    if (i < N_NODES) g_rowstart[i] = x - v + warp_sums[wid];
}

// ---------------- scan phase 2: scan 49 block sums (one warp) --------------
__global__ void k_scan2() {
    const int lane = threadIdx.x;      // 32 threads
    int v0 = (2 * lane     < SCAN_NB) ? g_blocksum[2 * lane]     : 0;
    int v1 = (2 * lane + 1 < SCAN_NB) ? g_blocksum[2 * lane + 1] : 0;
    int pair = v0 + v1;
    int x = pair;
#pragma unroll
    for (int off = 1; off < 32; off <<= 1) {
        int y = __shfl_up_sync(0xffffffffu, x, off);
        if (lane >= off) x += y;
    }
    int excl = x - pair;
    if (2 * lane     < SCAN_NB) g_blockoff[2 * lane]     = excl;
    if (2 * lane + 1 < SCAN_NB) g_blockoff[2 * lane + 1] = excl + v0;
}

// ---------------- scan phase 3: add offsets, init cursor -------------------
__global__ void k_scan3() {
    int i = blockIdx.x * blockDim.x + threadIdx.x;
    if (i < N_NODES) {
        int v = g_rowstart[i] + g_blockoff[i >> 10];
        g_rowstart[i] = v;
        g_cursor[i]   = v;
    }
    if (i == 0) g_rowstart[N_NODES] = E_TOT;   // total is a known constant
}

// ---------------- CSR build: scatter ---------------------------------------
__global__ void k_scatter(const int* __restrict__ ei) {
    int i = blockIdx.x * blockDim.x + threadIdx.x;
    int stride = gridDim.x * blockDim.x;
    for (int e = i; e < E_TOT; e += stride) {
        int s, d;
        if (e < E_EDGES) { s = __ldg(ei + e); d = __ldg(ei + E_EDGES + e); }
        else             { s = e - E_EDGES;   d = s; }
        int pos = atomicAdd(&g_cursor[d], 1);
        g_csr_src[pos] = s;
    }
}

// ---------------- fused softmax + aggregation + bias + relu ----------------
__global__ __launch_bounds__(256) void k_agg(float* __restrict__ out,
                                             const float* __restrict__ bias) {
    const int lane = threadIdx.x & 31;
    const int d = (blockIdx.x * blockDim.x + threadIdx.x) >> 5;
    if (d >= N_NODES) return;

    const int rs = g_rowstart[d];
    const int re = g_rowstart[d + 1];
    const float add = __ldg(g_ad + d);

    float4 acc = make_float4(0.f, 0.f, 0.f, 0.f);
    float den = 0.f;

    for (int base = rs; base < re; base += 32) {
        int j = base + lane;
        int s = 0; float ex = 0.f;
        if (j < re) {
            s = __ldg(g_csr_src + j);
            float e = __ldg(g_as + s) + add;
            e = e > 0.f ? e : 0.2f * e;
            ex = __expf(e);
            den += ex;
        }
        int m = re - base;
        if (m >= 32) {
#pragma unroll 8
            for (int k = 0; k < 32; k++) {
                int   ss = __shfl_sync(0xffffffffu, s, k);
                float ee = __shfl_sync(0xffffffffu, ex, k);
                const float4 hv = *(const float4*)(g_h + (size_t)ss * C + lane * 4);
                acc.x = fmaf(ee, hv.x, acc.x);
                acc.y = fmaf(ee, hv.y, acc.y);
                acc.z = fmaf(ee, hv.z, acc.z);
                acc.w = fmaf(ee, hv.w, acc.w);
            }
        } else {
            for (int k = 0; k < m; k++) {
                int   ss = __shfl_sync(0xffffffffu, s, k);
                float ee = __shfl_sync(0xffffffffu, ex, k);
                const float4 hv = *(const float4*)(g_h + (size_t)ss * C + lane * 4);
                acc.x = fmaf(ee, hv.x, acc.x);
                acc.y = fmaf(ee, hv.y, acc.y);
                acc.z = fmaf(ee, hv.z, acc.z);
                acc.w = fmaf(ee, hv.w, acc.w);
            }
        }
    }

#pragma unroll
    for (int off = 16; off; off >>= 1)
        den += __shfl_xor_sync(0xffffffffu, den, off);
    const float inv = 1.f / (den + 1e-16f);

    const float4 b = *(const float4*)(bias + lane * 4);
    float4 v;
    v.x = fmaxf(fmaf(acc.x, inv, b.x), 0.f);
    v.y = fmaxf(fmaf(acc.y, inv, b.y), 0.f);
    v.z = fmaxf(fmaf(acc.z, inv, b.z), 0.f);
    v.w = fmaxf(fmaf(acc.w, inv, b.w), 0.f);
    *(float4*)(out + (size_t)d * C + lane * 4) = v;
}

// ---------------- launch ---------------------------------------------------
extern "C" void kernel_launch(void* const* d_in, const int* in_sizes, int n_in,
                              void* d_out, int out_size) {
    const float* x     = (const float*)d_in[0];
    const float* W     = (const float*)d_in[1];
    const float* a_src = (const float*)d_in[2];
    const float* a_dst = (const float*)d_in[3];
    const float* bias  = (const float*)d_in[4];
    const int*   ei    = (const int*)d_in[5];
    float* out = (float*)d_out;

    k_zero<<<(N_NODES + 255) / 256, 256>>>();
    k_gemm<<<(N_NODES + 63) / 64, 256>>>(x, W, a_src, a_dst);
    k_count<<<2048, 256>>>(ei);
    k_scan1<<<SCAN_NB, 1024>>>();
    k_scan2<<<1, 32>>>();
    k_scan3<<<(N_NODES + 255) / 256, 256>>>();
    k_scatter<<<2048, 256>>>(ei);
    k_agg<<<(N_NODES * 32 + 255) / 256, 256>>>(out, bias);
}